// round 12
// baseline (speedup 1.0000x reference)
#include <cuda_runtime.h>
#include <math.h>
#include <stdint.h>

#define NN 50000
#define EE 800000
#define CC 64
#define NT32 25000          // EE/32 warp tiles

// -------- device scratch --------
__device__ float g_v[NN*CC];       // h@W_lin + bp2   (bp2 folded)
__device__ float g_bsrc[NN*CC];    // h@(W_src@Wa1)
__device__ float g_bdst[NN*CC];    // h@(W_dst@Wa1) + cfuse   (cfuse folded)
__device__ float g_sum[NN*CC];
__device__ float g_num[NN*CC];
__device__ float g_Wsa[CC*CC];
__device__ float g_Wda[CC*CC];
__device__ float g_Wfuse[CC*CC];   // Wp2@Wa1
__device__ float g_cfuse[CC];      // bp2@Wa1 + ba1
__device__ uint32_t g_fW[5][4096]; // tf32 frag-linear: Win|Wlin|Wsa|Wda|Wout

// ================= mma.sync helpers =================
__device__ __forceinline__ uint32_t f2tf(float f) {
  uint32_t o;
  asm("cvt.rna.tf32.f32 %0, %1;" : "=r"(o) : "f"(f));
  return o;
}
__device__ __forceinline__ uint32_t packbf(float lo, float hi) {
  uint32_t o;
  asm("cvt.rn.bf16x2.f32 %0, %1, %2;" : "=r"(o) : "f"(hi), "f"(lo));
  return o;
}
__device__ __forceinline__ void mma8(float c[4], uint32_t a0, uint32_t a1,
                                     uint32_t a2, uint32_t a3,
                                     uint32_t b0, uint32_t b1) {
  asm volatile(
      "mma.sync.aligned.m16n8k8.row.col.f32.tf32.tf32.f32 "
      "{%0,%1,%2,%3}, {%4,%5,%6,%7}, {%8,%9}, {%0,%1,%2,%3};"
      : "+f"(c[0]), "+f"(c[1]), "+f"(c[2]), "+f"(c[3])
      : "r"(a0), "r"(a1), "r"(a2), "r"(a3), "r"(b0), "r"(b1));
}
__device__ __forceinline__ void mma16(float c[4], uint32_t a0, uint32_t a1,
                                      uint32_t a2, uint32_t a3,
                                      uint32_t b0, uint32_t b1) {
  asm volatile(
      "mma.sync.aligned.m16n8k16.row.col.f32.bf16.bf16.f32 "
      "{%0,%1,%2,%3}, {%4,%5,%6,%7}, {%8,%9}, {%0,%1,%2,%3};"
      : "+f"(c[0]), "+f"(c[1]), "+f"(c[2]), "+f"(c[3])
      : "r"(a0), "r"(a1), "r"(a2), "r"(a3), "r"(b0), "r"(b1));
}
__device__ __forceinline__ void redv4(float* p, float a, float b, float c, float d) {
  asm volatile("red.global.add.v4.f32 [%0], {%1,%2,%3,%4};"
               :: "l"(p), "f"(a), "f"(b), "f"(c), "f"(d) : "memory");
}

// ---- tf32 warp GEMM (M=16), A in regs, B frag-linear ----
__device__ __forceinline__ void wgemmr_tf(const uint32_t A[8][4],
                                          const uint32_t* __restrict__ B,
                                          int lane, float D[8][4]) {
#pragma unroll
  for (int n8 = 0; n8 < 8; n8++)
#pragma unroll
    for (int j = 0; j < 4; j++) D[n8][j] = 0.f;
#pragma unroll
  for (int k8 = 0; k8 < 8; k8++) {
    const uint32_t* bb = B + (k8<<9) + (lane<<1);
#pragma unroll
    for (int n8 = 0; n8 < 8; n8++) {
      uint2 w = *(const uint2*)(bb + (n8<<6));
      mma8(D[n8], A[k8][0], A[k8][1], A[k8][2], A[k8][3], w.x, w.y);
    }
  }
}

// ---- bf16 warp GEMM (M=32): two A-halves share every B load ----
__device__ __forceinline__ void wgemm32(const uint32_t A[2][4][4],
                                        const uint32_t* __restrict__ sB,
                                        int lane, float D[2][8][4]) {
#pragma unroll
  for (int m = 0; m < 2; m++)
#pragma unroll
    for (int n8 = 0; n8 < 8; n8++)
#pragma unroll
      for (int j = 0; j < 4; j++) D[m][n8][j] = 0.f;
#pragma unroll
  for (int ks = 0; ks < 4; ks++) {
    const uint32_t* bb = sB + (ks<<9) + (lane<<1);
#pragma unroll
    for (int n8 = 0; n8 < 8; n8++) {
      uint2 w = *(const uint2*)(bb + (n8<<6));
      mma16(D[0][n8], A[0][ks][0], A[0][ks][1], A[0][ks][2], A[0][ks][3], w.x, w.y);
      mma16(D[1][n8], A[1][ks][0], A[1][ks][1], A[1][ks][2], A[1][ks][3], w.x, w.y);
    }
  }
}

// stage fp32 weight [64][64] into tf32 frag-linear (4096 words)
__device__ __forceinline__ void stage_tf32(const float* __restrict__ W,
                                           uint32_t* __restrict__ dst, int tid) {
  for (int idx = tid; idx < 4096; idx += 256) {
    int tbit = idx & 1;
    int ln   = (idx & 63) >> 1;
    int kn   = idx >> 6;
    int k8 = kn >> 3, n8 = kn & 7;
    int rr = ln >> 2, qq = ln & 3;
    dst[idx] = f2tf(W[(k8*8 + qq + tbit*4)*64 + n8*8 + rr]);
  }
}

// ---------------- KW: weight-product precompute ----------------
__global__ __launch_bounds__(256) void kw(const float* __restrict__ Wsrc,
    const float* __restrict__ Wdst, const float* __restrict__ Wp2,
    const float* __restrict__ Wa1, const float* __restrict__ bp2,
    const float* __restrict__ ba1) {
  __shared__ float sWa1[4096];
  int tid = threadIdx.x;
#pragma unroll
  for (int t = 0; t < 16; t++) sWa1[t*256 + tid] = Wa1[t*256 + tid];
  __syncthreads();
  const float* A = (blockIdx.x == 0) ? Wsrc : (blockIdx.x == 1) ? Wdst : Wp2;
  float* O = (blockIdx.x == 0) ? g_Wsa : (blockIdx.x == 1) ? g_Wda : g_Wfuse;
  for (int idx = tid; idx < 4096; idx += 256) {
    int k = idx >> 6, n = idx & 63;
    float s = 0.f;
#pragma unroll 16
    for (int m = 0; m < 64; m++) s = fmaf(A[k*64 + m], sWa1[m*64 + n], s);
    O[idx] = s;
  }
  if (blockIdx.x == 2 && tid < 64) {
    float s = ba1[tid];
#pragma unroll 16
    for (int m = 0; m < 64; m++) s = fmaf(bp2[m], sWa1[m*64 + tid], s);
    g_cfuse[tid] = s;
  }
}

// ---------------- KW2: one-time tf32 frag-linear staging ----------------
__global__ __launch_bounds__(256) void kw2(const float* __restrict__ Win,
                                           const float* __restrict__ Wlin,
                                           const float* __restrict__ Wout) {
  int b = blockIdx.x;
  const float* src = (b == 0) ? Win : (b == 1) ? Wlin
                   : (b == 2) ? g_Wsa : (b == 3) ? g_Wda : Wout;
  stage_tf32(src, g_fW[b], threadIdx.x);
}

// ---------------- K1: node projections (tf32 mma, global B-frags) ----------
__global__ __launch_bounds__(256, 2) void k_node(const float* __restrict__ x,
                                                 const float* __restrict__ bin,
                                                 const float* __restrict__ bp2) {
  __shared__ float sXall[8*1088];
  __shared__ float sbin[64];
  __shared__ float sAdd[3][64];   // [0]=bp2 (fold into v), [1]=0, [2]=cfuse

  int tid = threadIdx.x;
  int wid = tid >> 5, lane = tid & 31;
  int nb0 = blockIdx.x * 128;

#pragma unroll
  for (int j = 0; j < 8; j++) {
    int idx = j*256 + tid;
    int node = nb0 + (idx >> 4);
    int c4 = (idx & 15) << 2;
    if (node < NN) {
      float4 z = make_float4(0.f,0.f,0.f,0.f);
      *(float4*)(g_sum + node*64 + c4) = z;
      *(float4*)(g_num + node*64 + c4) = z;
    }
  }
  if (tid < 64) {
    sbin[tid] = bin[tid];
    sAdd[0][tid] = bp2[tid];
    sAdd[1][tid] = 0.f;
    sAdd[2][tid] = g_cfuse[tid];
  }
  __syncthreads();

  int nb = nb0 + wid*16;
  if (nb >= NN) return;
  float* sX = sXall + wid*1088;

  for (int idx = lane; idx < 256; idx += 32) {
    int row = idx >> 4;
    int c4  = (idx & 15) << 2;
    int n = nb + row;
    float4 v = make_float4(0.f,0.f,0.f,0.f);
    if (n < NN) v = *(const float4*)(x + n*64 + c4);
    *(float4*)(sX + row*68 + c4) = v;
  }
  __syncwarp();

  int r = lane >> 2, q = lane & 3;
  int Slo = (lane & ~3) | (q >> 1);
  int Shi = Slo + 2;
  int odd = q & 1;

  uint32_t Ax[8][4];
#pragma unroll
  for (int k8 = 0; k8 < 8; k8++) {
    Ax[k8][0] = f2tf(sX[r*68     + k8*8 + q]);
    Ax[k8][1] = f2tf(sX[(r+8)*68 + k8*8 + q]);
    Ax[k8][2] = f2tf(sX[r*68     + k8*8 + q + 4]);
    Ax[k8][3] = f2tf(sX[(r+8)*68 + k8*8 + q + 4]);
  }

  float Dh[8][4];
  wgemmr_tf(Ax, g_fW[0], lane, Dh);
  uint32_t Ah[8][4];
#pragma unroll
  for (int n8 = 0; n8 < 8; n8++) {
    int c0 = n8*8 + 2*q, c1 = c0 + 1;
    uint32_t u0 = f2tf(fmaxf(Dh[n8][0] + sbin[c0], 0.f));
    uint32_t u1 = f2tf(fmaxf(Dh[n8][1] + sbin[c1], 0.f));
    uint32_t u2 = f2tf(fmaxf(Dh[n8][2] + sbin[c0], 0.f));
    uint32_t u3 = f2tf(fmaxf(Dh[n8][3] + sbin[c1], 0.f));
    uint32_t v0 = __shfl_sync(0xFFFFFFFFu, u0, Slo);
    uint32_t v1 = __shfl_sync(0xFFFFFFFFu, u1, Slo);
    Ah[n8][0] = odd ? v1 : v0;
    uint32_t v2 = __shfl_sync(0xFFFFFFFFu, u2, Slo);
    uint32_t v3 = __shfl_sync(0xFFFFFFFFu, u3, Slo);
    Ah[n8][1] = odd ? v3 : v2;
    uint32_t w0 = __shfl_sync(0xFFFFFFFFu, u0, Shi);
    uint32_t w1 = __shfl_sync(0xFFFFFFFFu, u1, Shi);
    Ah[n8][2] = odd ? w1 : w0;
    uint32_t w2 = __shfl_sync(0xFFFFFFFFu, u2, Shi);
    uint32_t w3 = __shfl_sync(0xFFFFFFFFu, u3, Shi);
    Ah[n8][3] = odd ? w3 : w2;
  }

  int ok0 = (nb + r < NN), ok1 = (nb + r + 8 < NN);
#pragma unroll
  for (int m = 0; m < 3; m++) {
    float* Om = (m==0) ? g_v : (m==1) ? g_bsrc : g_bdst;
    const float* ad = sAdd[m];
    float D[8][4];
    wgemmr_tf(Ah, g_fW[m+1], lane, D);
#pragma unroll
    for (int n8 = 0; n8 < 8; n8++) {
      int c0 = n8*8 + 2*q, c1 = c0 + 1;
      if (ok0) *(float2*)(Om + (nb+r)*64 + c0) =
          make_float2(D[n8][0] + ad[c0], D[n8][1] + ad[c1]);
      if (ok1) *(float2*)(Om + (nb+r+8)*64 + c0) =
          make_float2(D[n8][2] + ad[c0], D[n8][3] + ad[c1]);
    }
  }
}

// ---------------- K2: fused edge kernel (bf16, M=32 per warp) ----------------
// 192 threads / 6 warps. smem words:
//  [0,6144)      3 weights frag-linear bf16 (Wp2 | Wfuse | Wa2)
//  [6144,6400)   Wp1 packed float4 per col {w0,w1,w2,bp1}
//  [6400,6464)   ba2
//  [6464,...)    per-warp 3520: bufD1[32x68] | bufH[32x40] | idx[64]
#define EW_WORDS (6464 + 6*3520)
__global__ void __launch_bounds__(192, 2) k_edge(
    const float* __restrict__ pos, const int* __restrict__ eidx,
    const float* __restrict__ Wp1, const float* __restrict__ bp1,
    const float* __restrict__ Wp2, const float* __restrict__ Wa2,
    const float* __restrict__ ba2) {
  extern __shared__ uint32_t smu[];
  uint32_t* sW    = smu;                    // 6144
  float4*   sWp1p = (float4*)(smu + 6144);  // 64
  float*    sba2  = (float*)(smu + 6400);   // 64

  int tid = threadIdx.x;
  int wid = tid >> 5, lane = tid & 31;

  // stage 3 bf16 weights frag-linear: frag(ks,n8) at (ks*8+n8)*64 + ln*2 + t
  for (int idx = tid; idx < 6144; idx += 192) {
    int m = idx >> 11;
    int i2 = idx & 2047;
    const float* W = (m == 0) ? Wp2 : (m == 1) ? g_Wfuse : Wa2;
    int t  = i2 & 1;
    int ln = (i2 >> 1) & 31;
    int fr = i2 >> 6;
    int ks = fr >> 3, n8 = fr & 7;
    int rr = ln >> 2, qq = ln & 3;
    int klo = 16*ks + 2*qq + t*8;
    int col = 8*n8 + rr;
    sW[(m<<11) + (fr<<6) + (ln<<1) + t] =
        packbf(W[klo*64 + col], W[(klo+1)*64 + col]);
  }
  if (tid < 64) {
    sWp1p[tid] = make_float4(Wp1[tid], Wp1[64+tid], Wp1[128+tid], bp1[tid]);
    sba2[tid] = ba2[tid];
  }
  __syncthreads();

  float* bufD1 = (float*)(smu + 6464 + wid*3520);       // 32 x 68
  float* bufH  = bufD1 + 2176;                          // 32 x 40
  int*   sS    = (int*)(bufH + 1280);                   // 32
  int*   sD    = sS + 32;

  const uint32_t* sW1 = sW;            // Wp2
  const uint32_t* sW2 = sW + 2048;     // Wfuse
  const uint32_t* sW3 = sW + 4096;     // Wa2

  int r = lane >> 2, q = lane & 3;
  int eg = lane >> 3, c8 = lane & 7;

  int gw = blockIdx.x * 6 + wid;
  int nwarp = gridDim.x * 6;
  for (int t = gw; t < NT32; t += nwarp) {
    int eb = t * 32;
    int sn_me = eidx[eb + lane];
    int dn_me = eidx[EE + eb + lane];
    sS[lane] = sn_me;
    sD[lane] = dn_me;
    float rx = pos[dn_me*3+0] - pos[sn_me*3+0];
    float ry = pos[dn_me*3+1] - pos[sn_me*3+1];
    float rz = pos[dn_me*3+2] - pos[sn_me*3+2];
    __syncwarp();

    // ---- t-fragments for both M-halves (shfl rel, fma, pack bf16) ----
    uint32_t At[2][4][4];
#pragma unroll
    for (int m = 0; m < 2; m++) {
      float rxl = __shfl_sync(0xFFFFFFFFu, rx, m*16 + r);
      float ryl = __shfl_sync(0xFFFFFFFFu, ry, m*16 + r);
      float rzl = __shfl_sync(0xFFFFFFFFu, rz, m*16 + r);
      float rxh = __shfl_sync(0xFFFFFFFFu, rx, m*16 + r + 8);
      float ryh = __shfl_sync(0xFFFFFFFFu, ry, m*16 + r + 8);
      float rzh = __shfl_sync(0xFFFFFFFFu, rz, m*16 + r + 8);
#pragma unroll
      for (int ks = 0; ks < 4; ks++) {
        float4 wA = sWp1p[16*ks + 2*q];
        float4 wB = sWp1p[16*ks + 2*q + 1];
        float4 wC = sWp1p[16*ks + 2*q + 8];
        float4 wD = sWp1p[16*ks + 2*q + 9];
        float a0 = fmaxf(fmaf(rxl,wA.x,fmaf(ryl,wA.y,fmaf(rzl,wA.z,wA.w))),0.f);
        float b0 = fmaxf(fmaf(rxl,wB.x,fmaf(ryl,wB.y,fmaf(rzl,wB.z,wB.w))),0.f);
        float a1 = fmaxf(fmaf(rxh,wA.x,fmaf(ryh,wA.y,fmaf(rzh,wA.z,wA.w))),0.f);
        float b1 = fmaxf(fmaf(rxh,wB.x,fmaf(ryh,wB.y,fmaf(rzh,wB.z,wB.w))),0.f);
        float c0 = fmaxf(fmaf(rxl,wC.x,fmaf(ryl,wC.y,fmaf(rzl,wC.z,wC.w))),0.f);
        float d0 = fmaxf(fmaf(rxl,wD.x,fmaf(ryl,wD.y,fmaf(rzl,wD.z,wD.w))),0.f);
        float c1 = fmaxf(fmaf(rxh,wC.x,fmaf(ryh,wC.y,fmaf(rzh,wC.z,wC.w))),0.f);
        float d1 = fmaxf(fmaf(rxh,wD.x,fmaf(ryh,wD.y,fmaf(rzh,wD.z,wD.w))),0.f);
        At[m][ks][0] = packbf(a0, b0);
        At[m][ks][1] = packbf(a1, b1);
        At[m][ks][2] = packbf(c0, d0);
        At[m][ks][3] = packbf(c1, d1);
      }
    }

    // ---- GEMM D1 = t@Wp2 (delta pre-bias), dump full to bufD1 ----
    {
      float D1[2][8][4];
      wgemm32(At, sW1, lane, D1);
#pragma unroll
      for (int m = 0; m < 2; m++)
#pragma unroll
        for (int n8 = 0; n8 < 8; n8++) {
          int c0 = n8*8 + 2*q;
          *(float2*)(bufD1 + (16*m+r)*68 + c0)   = make_float2(D1[m][n8][0], D1[m][n8][1]);
          *(float2*)(bufD1 + (16*m+r+8)*68 + c0) = make_float2(D1[m][n8][2], D1[m][n8][3]);
        }
    }

    // ---- GEMM D2 = t@Wfuse ----
    float D2[2][8][4];
    wgemm32(At, sW2, lane, D2);

    // ---- epi1: per n-half gather g = bdst - bsrc (cfuse folded), build Au ----
    uint32_t Au[2][4][4];
#pragma unroll
    for (int h = 0; h < 2; h++) {
      __syncwarp();
#pragma unroll
      for (int s8 = 0; s8 < 8; s8++) {
        int e = s8*4 + eg;
        int dn = sD[e], sn = sS[e];
        int cg = h*32 + c8*4;
        float4 bd = *(const float4*)(g_bdst + dn*64 + cg);
        float4 bs = *(const float4*)(g_bsrc + sn*64 + cg);
        *(float4*)(bufH + e*40 + c8*4) = make_float4(
            bd.x - bs.x, bd.y - bs.y, bd.z - bs.z, bd.w - bs.w);
      }
      __syncwarp();
#pragma unroll
      for (int m = 0; m < 2; m++)
#pragma unroll
        for (int kk = 0; kk < 2; kk++) {
          int ks = 2*h + kk;
          int row = 16*m + r;
          int loc = kk*16 + 2*q;
          float2 ga = *(const float2*)(bufH + row*40 + loc);
          float2 gb = *(const float2*)(bufH + (row+8)*40 + loc);
          float2 gc = *(const float2*)(bufH + row*40 + loc + 8);
          float2 gd = *(const float2*)(bufH + (row+8)*40 + loc + 8);
          int na = 2*ks, nb2 = 2*ks + 1;
          Au[m][ks][0] = packbf(fmaxf(D2[m][na][0] + ga.x, 0.f),
                                fmaxf(D2[m][na][1] + ga.y, 0.f));
          Au[m][ks][1] = packbf(fmaxf(D2[m][na][2] + gb.x, 0.f),
                                fmaxf(D2[m][na][3] + gb.y, 0.f));
          Au[m][ks][2] = packbf(fmaxf(D2[m][nb2][0] + gc.x, 0.f),
                                fmaxf(D2[m][nb2][1] + gc.y, 0.f));
          Au[m][ks][3] = packbf(fmaxf(D2[m][nb2][2] + gd.x, 0.f),
                                fmaxf(D2[m][nb2][3] + gd.y, 0.f));
        }
    }

    // ---- GEMM D3 = u@Wa2 ----
    float D3[2][8][4];
    wgemm32(Au, sW3, lane, D3);

    // ---- epi2 per n-half: e = exp(D3+ba2); red sum/num ----
#pragma unroll
    for (int h = 0; h < 2; h++) {
      __syncwarp();
#pragma unroll
      for (int m = 0; m < 2; m++)
#pragma unroll
        for (int n8l = 0; n8l < 4; n8l++) {
          int n8 = 4*h + n8l;
          int cl = n8l*8 + 2*q;
          *(float2*)(bufH + (16*m+r)*40 + cl)   = make_float2(D3[m][n8][0], D3[m][n8][1]);
          *(float2*)(bufH + (16*m+r+8)*40 + cl) = make_float2(D3[m][n8][2], D3[m][n8][3]);
        }
      __syncwarp();
#pragma unroll
      for (int s8 = 0; s8 < 8; s8++) {
        int e = s8*4 + eg;
        int dn = sD[e], sn = sS[e];
        int cg = h*32 + c8*4;
        float4 lg = *(const float4*)(bufH + e*40 + c8*4);
        float4 d1 = *(const float4*)(bufD1 + e*68 + cg);
        float4 vv = *(const float4*)(g_v + sn*64 + cg);   // bp2 folded in
        float4 ba = *(const float4*)(sba2 + cg);
        float e0 = __expf(lg.x + ba.x);
        float e1 = __expf(lg.y + ba.y);
        float e2 = __expf(lg.z + ba.z);
        float e3 = __expf(lg.w + ba.w);
        redv4(g_sum + dn*64 + cg, e0, e1, e2, e3);
        redv4(g_num + dn*64 + cg,
              e0 * (vv.x + d1.x), e1 * (vv.y + d1.y),
              e2 * (vv.z + d1.z), e3 * (vv.w + d1.w));
      }
    }
    __syncwarp();
  }
}

// ---------------- K3: out = relu((num/(sum+eps))@W_out + b_out), tf32 -------
__global__ __launch_bounds__(256, 2) void k_final(const float* __restrict__ bout,
                                                  float* __restrict__ out) {
  __shared__ float sXall[8*1088];
  __shared__ float sbout[64];

  int tid = threadIdx.x;
  int wid = tid >> 5, lane = tid & 31;
  int nb = blockIdx.x * 128 + wid*16;

  if (tid < 64) sbout[tid] = bout[tid];
  __syncthreads();

  if (nb >= NN) return;
  float* sX = sXall + wid*1088;

  for (int idx = lane; idx < 256; idx += 32) {
    int row = idx >> 4;
    int c4  = (idx & 15) << 2;
    int n = nb + row;
    float4 v = make_float4(0.f,0.f,0.f,0.f);
    if (n < NN) {
      float4 num = *(const float4*)(g_num + n*64 + c4);
      float4 s   = *(const float4*)(g_sum + n*64 + c4);
      v.x = num.x / (s.x + 1e-16f);
      v.y = num.y / (s.y + 1e-16f);
      v.z = num.z / (s.z + 1e-16f);
      v.w = num.w / (s.w + 1e-16f);
    }
    *(float4*)(sX + row*68 + c4) = v;
  }
  __syncwarp();

  int r = lane >> 2, q = lane & 3;
  uint32_t Ax[8][4];
#pragma unroll
  for (int k8 = 0; k8 < 8; k8++) {
    Ax[k8][0] = f2tf(sX[r*68     + k8*8 + q]);
    Ax[k8][1] = f2tf(sX[(r+8)*68 + k8*8 + q]);
    Ax[k8][2] = f2tf(sX[r*68     + k8*8 + q + 4]);
    Ax[k8][3] = f2tf(sX[(r+8)*68 + k8*8 + q + 4]);
  }

  float D[8][4];
  wgemmr_tf(Ax, g_fW[4], lane, D);

  int ok0 = (nb + r < NN), ok1 = (nb + r + 8 < NN);
#pragma unroll
  for (int n8 = 0; n8 < 8; n8++) {
    int c0 = n8*8 + 2*q, c1 = c0 + 1;
    if (ok0)
      *(float2*)(out + (nb+r)*64 + c0) = make_float2(
          fmaxf(D[n8][0] + sbout[c0], 0.f), fmaxf(D[n8][1] + sbout[c1], 0.f));
    if (ok1)
      *(float2*)(out + (nb+r+8)*64 + c0) = make_float2(
          fmaxf(D[n8][2] + sbout[c0], 0.f), fmaxf(D[n8][3] + sbout[c1], 0.f));
  }
}

// ---------------- launch ----------------
extern "C" void kernel_launch(void* const* d_in, const int* in_sizes, int n_in,
                              void* d_out, int out_size) {
  const float* x    = (const float*)d_in[0];
  const float* pos  = (const float*)d_in[1];
  const int*   eidx = (const int*)  d_in[2];
  const float* W_in = (const float*)d_in[3];
  const float* b_in = (const float*)d_in[4];
  const float* W_lin= (const float*)d_in[5];
  const float* W_src= (const float*)d_in[6];
  const float* W_dst= (const float*)d_in[7];
  const float* Wp1  = (const float*)d_in[8];
  const float* bp1  = (const float*)d_in[9];
  const float* Wp2  = (const float*)d_in[10];
  const float* bp2  = (const float*)d_in[11];
  const float* Wa1  = (const float*)d_in[12];
  const float* ba1  = (const float*)d_in[13];
  const float* Wa2  = (const float*)d_in[14];
  const float* ba2  = (const float*)d_in[15];
  const float* W_out= (const float*)d_in[16];
  const float* b_out= (const float*)d_in[17];
  float* out = (float*)d_out;

  cudaFuncSetAttribute(k_edge, cudaFuncAttributeMaxDynamicSharedMemorySize,
                       EW_WORDS * 4);

  kw<<<3, 256>>>(W_src, W_dst, Wp2, Wa1, bp2, ba1);
  kw2<<<5, 256>>>(W_in, W_lin, W_out);
  k_node<<<(NN + 127) / 128, 256>>>(x, b_in, bp2);
  k_edge<<<296, 192, EW_WORDS * 4>>>(pos, eidx, Wp1, bp1, Wp2, Wa2, ba2);
  k_final<<<(NN + 127) / 128, 256>>>(b_out, out);
}

// round 13
// speedup vs baseline: 1.1555x; 1.1555x over previous
#include <cuda_runtime.h>
#include <math.h>
#include <stdint.h>

#define NN 50000
#define EE 800000
#define CC 64
#define NT16 50000          // EE/16 warp tiles

// -------- device scratch --------
__device__ float g_v[NN*CC];       // h@W_lin + bp2   (bp2 folded)
__device__ float g_bsrc[NN*CC];    // h@(W_src@Wa1)
__device__ float g_bdst[NN*CC];    // h@(W_dst@Wa1) + cfuse   (cfuse folded)
__device__ float g_sum[NN*CC];
__device__ float g_num[NN*CC];
__device__ float g_Wsa[CC*CC];
__device__ float g_Wda[CC*CC];
__device__ float g_Wfuse[CC*CC];   // Wp2@Wa1
__device__ float g_cfuse[CC];      // bp2@Wa1 + ba1
__device__ uint32_t g_fW[5][4096]; // tf32 frag-linear: Win|Wlin|Wsa|Wda|Wout

// ================= mma.sync helpers =================
__device__ __forceinline__ uint32_t f2tf(float f) {
  uint32_t o;
  asm("cvt.rna.tf32.f32 %0, %1;" : "=r"(o) : "f"(f));
  return o;
}
__device__ __forceinline__ uint32_t packbf(float lo, float hi) {
  uint32_t o;
  asm("cvt.rn.bf16x2.f32 %0, %1, %2;" : "=r"(o) : "f"(hi), "f"(lo));
  return o;
}
__device__ __forceinline__ void mma8(float c[4], uint32_t a0, uint32_t a1,
                                     uint32_t a2, uint32_t a3,
                                     uint32_t b0, uint32_t b1) {
  asm volatile(
      "mma.sync.aligned.m16n8k8.row.col.f32.tf32.tf32.f32 "
      "{%0,%1,%2,%3}, {%4,%5,%6,%7}, {%8,%9}, {%0,%1,%2,%3};"
      : "+f"(c[0]), "+f"(c[1]), "+f"(c[2]), "+f"(c[3])
      : "r"(a0), "r"(a1), "r"(a2), "r"(a3), "r"(b0), "r"(b1));
}
__device__ __forceinline__ void mma16(float c[4], uint32_t a0, uint32_t a1,
                                      uint32_t a2, uint32_t a3,
                                      uint32_t b0, uint32_t b1) {
  asm volatile(
      "mma.sync.aligned.m16n8k16.row.col.f32.bf16.bf16.f32 "
      "{%0,%1,%2,%3}, {%4,%5,%6,%7}, {%8,%9}, {%0,%1,%2,%3};"
      : "+f"(c[0]), "+f"(c[1]), "+f"(c[2]), "+f"(c[3])
      : "r"(a0), "r"(a1), "r"(a2), "r"(a3), "r"(b0), "r"(b1));
}
__device__ __forceinline__ void redv4(float* p, float a, float b, float c, float d) {
  asm volatile("red.global.add.v4.f32 [%0], {%1,%2,%3,%4};"
               :: "l"(p), "f"(a), "f"(b), "f"(c), "f"(d) : "memory");
}

// ---- tf32 warp GEMM (M=16), A in regs, B frag-linear ----
__device__ __forceinline__ void wgemmr_tf(const uint32_t A[8][4],
                                          const uint32_t* __restrict__ B,
                                          int lane, float D[8][4]) {
#pragma unroll
  for (int n8 = 0; n8 < 8; n8++)
#pragma unroll
    for (int j = 0; j < 4; j++) D[n8][j] = 0.f;
#pragma unroll
  for (int k8 = 0; k8 < 8; k8++) {
    const uint32_t* bb = B + (k8<<9) + (lane<<1);
#pragma unroll
    for (int n8 = 0; n8 < 8; n8++) {
      uint2 w = *(const uint2*)(bb + (n8<<6));
      mma8(D[n8], A[k8][0], A[k8][1], A[k8][2], A[k8][3], w.x, w.y);
    }
  }
}

// ---- bf16 dual warp GEMM (B1|B2 interleaved uint4) and single GEMM ----
__device__ __forceinline__ void wgemm2rb(const uint32_t A[4][4],
                                         const uint32_t* __restrict__ sW12,
                                         int lane, float D1[8][4], float D2[8][4]) {
#pragma unroll
  for (int n8 = 0; n8 < 8; n8++)
#pragma unroll
    for (int j = 0; j < 4; j++) { D1[n8][j] = 0.f; D2[n8][j] = 0.f; }
#pragma unroll
  for (int ks = 0; ks < 4; ks++) {
    const uint32_t* b = sW12 + (ks<<10) + (lane<<2);
#pragma unroll
    for (int n8 = 0; n8 < 8; n8++) {
      uint4 w = *(const uint4*)(b + (n8<<7));
      mma16(D1[n8], A[ks][0], A[ks][1], A[ks][2], A[ks][3], w.x, w.y);
      mma16(D2[n8], A[ks][0], A[ks][1], A[ks][2], A[ks][3], w.z, w.w);
    }
  }
}
__device__ __forceinline__ void wgemmrb(const uint32_t A[4][4],
                                        const uint32_t* __restrict__ sB,
                                        int lane, float D[8][4]) {
#pragma unroll
  for (int n8 = 0; n8 < 8; n8++)
#pragma unroll
    for (int j = 0; j < 4; j++) D[n8][j] = 0.f;
#pragma unroll
  for (int ks = 0; ks < 4; ks++) {
    const uint32_t* bb = sB + (ks<<9) + (lane<<1);
#pragma unroll
    for (int n8 = 0; n8 < 8; n8++) {
      uint2 w = *(const uint2*)(bb + (n8<<6));
      mma16(D[n8], A[ks][0], A[ks][1], A[ks][2], A[ks][3], w.x, w.y);
    }
  }
}

// stage fp32 weight [64][64] into tf32 frag-linear (4096 words)
__device__ __forceinline__ void stage_tf32(const float* __restrict__ W,
                                           uint32_t* __restrict__ dst, int tid) {
  for (int idx = tid; idx < 4096; idx += 256) {
    int tbit = idx & 1;
    int ln   = (idx & 63) >> 1;
    int kn   = idx >> 6;
    int k8 = kn >> 3, n8 = kn & 7;
    int rr = ln >> 2, qq = ln & 3;
    dst[idx] = f2tf(W[(k8*8 + qq + tbit*4)*64 + n8*8 + rr]);
  }
}

// ---------------- KW: weight-product precompute ----------------
__global__ __launch_bounds__(256) void kw(const float* __restrict__ Wsrc,
    const float* __restrict__ Wdst, const float* __restrict__ Wp2,
    const float* __restrict__ Wa1, const float* __restrict__ bp2,
    const float* __restrict__ ba1) {
  __shared__ float sWa1[4096];
  int tid = threadIdx.x;
#pragma unroll
  for (int t = 0; t < 16; t++) sWa1[t*256 + tid] = Wa1[t*256 + tid];
  __syncthreads();
  const float* A = (blockIdx.x == 0) ? Wsrc : (blockIdx.x == 1) ? Wdst : Wp2;
  float* O = (blockIdx.x == 0) ? g_Wsa : (blockIdx.x == 1) ? g_Wda : g_Wfuse;
  for (int idx = tid; idx < 4096; idx += 256) {
    int k = idx >> 6, n = idx & 63;
    float s = 0.f;
#pragma unroll 16
    for (int m = 0; m < 64; m++) s = fmaf(A[k*64 + m], sWa1[m*64 + n], s);
    O[idx] = s;
  }
  if (blockIdx.x == 2 && tid < 64) {
    float s = ba1[tid];
#pragma unroll 16
    for (int m = 0; m < 64; m++) s = fmaf(bp2[m], sWa1[m*64 + tid], s);
    g_cfuse[tid] = s;
  }
}

// ---------------- KW2: one-time tf32 frag-linear staging ----------------
__global__ __launch_bounds__(256) void kw2(const float* __restrict__ Win,
                                           const float* __restrict__ Wlin,
                                           const float* __restrict__ Wout) {
  int b = blockIdx.x;
  const float* src = (b == 0) ? Win : (b == 1) ? Wlin
                   : (b == 2) ? g_Wsa : (b == 3) ? g_Wda : Wout;
  stage_tf32(src, g_fW[b], threadIdx.x);
}

// ---------------- K1: node projections (tf32 mma, global B-frags) ----------
__global__ __launch_bounds__(256, 2) void k_node(const float* __restrict__ x,
                                                 const float* __restrict__ bin,
                                                 const float* __restrict__ bp2) {
  __shared__ float sXall[8*1088];
  __shared__ float sbin[64];
  __shared__ float sAdd[3][64];   // [0]=bp2 (fold into v), [1]=0, [2]=cfuse

  int tid = threadIdx.x;
  int wid = tid >> 5, lane = tid & 31;
  int nb0 = blockIdx.x * 128;

#pragma unroll
  for (int j = 0; j < 8; j++) {
    int idx = j*256 + tid;
    int node = nb0 + (idx >> 4);
    int c4 = (idx & 15) << 2;
    if (node < NN) {
      float4 z = make_float4(0.f,0.f,0.f,0.f);
      *(float4*)(g_sum + node*64 + c4) = z;
      *(float4*)(g_num + node*64 + c4) = z;
    }
  }
  if (tid < 64) {
    sbin[tid] = bin[tid];
    sAdd[0][tid] = bp2[tid];
    sAdd[1][tid] = 0.f;
    sAdd[2][tid] = g_cfuse[tid];
  }
  __syncthreads();

  int nb = nb0 + wid*16;
  if (nb >= NN) return;
  float* sX = sXall + wid*1088;

  for (int idx = lane; idx < 256; idx += 32) {
    int row = idx >> 4;
    int c4  = (idx & 15) << 2;
    int n = nb + row;
    float4 v = make_float4(0.f,0.f,0.f,0.f);
    if (n < NN) v = *(const float4*)(x + n*64 + c4);
    *(float4*)(sX + row*68 + c4) = v;
  }
  __syncwarp();

  int r = lane >> 2, q = lane & 3;
  int Slo = (lane & ~3) | (q >> 1);
  int Shi = Slo + 2;
  int odd = q & 1;

  uint32_t Ax[8][4];
#pragma unroll
  for (int k8 = 0; k8 < 8; k8++) {
    Ax[k8][0] = f2tf(sX[r*68     + k8*8 + q]);
    Ax[k8][1] = f2tf(sX[(r+8)*68 + k8*8 + q]);
    Ax[k8][2] = f2tf(sX[r*68     + k8*8 + q + 4]);
    Ax[k8][3] = f2tf(sX[(r+8)*68 + k8*8 + q + 4]);
  }

  float Dh[8][4];
  wgemmr_tf(Ax, g_fW[0], lane, Dh);
  uint32_t Ah[8][4];
#pragma unroll
  for (int n8 = 0; n8 < 8; n8++) {
    int c0 = n8*8 + 2*q, c1 = c0 + 1;
    uint32_t u0 = f2tf(fmaxf(Dh[n8][0] + sbin[c0], 0.f));
    uint32_t u1 = f2tf(fmaxf(Dh[n8][1] + sbin[c1], 0.f));
    uint32_t u2 = f2tf(fmaxf(Dh[n8][2] + sbin[c0], 0.f));
    uint32_t u3 = f2tf(fmaxf(Dh[n8][3] + sbin[c1], 0.f));
    uint32_t v0 = __shfl_sync(0xFFFFFFFFu, u0, Slo);
    uint32_t v1 = __shfl_sync(0xFFFFFFFFu, u1, Slo);
    Ah[n8][0] = odd ? v1 : v0;
    uint32_t v2 = __shfl_sync(0xFFFFFFFFu, u2, Slo);
    uint32_t v3 = __shfl_sync(0xFFFFFFFFu, u3, Slo);
    Ah[n8][1] = odd ? v3 : v2;
    uint32_t w0 = __shfl_sync(0xFFFFFFFFu, u0, Shi);
    uint32_t w1 = __shfl_sync(0xFFFFFFFFu, u1, Shi);
    Ah[n8][2] = odd ? w1 : w0;
    uint32_t w2 = __shfl_sync(0xFFFFFFFFu, u2, Shi);
    uint32_t w3 = __shfl_sync(0xFFFFFFFFu, u3, Shi);
    Ah[n8][3] = odd ? w3 : w2;
  }

  int ok0 = (nb + r < NN), ok1 = (nb + r + 8 < NN);
#pragma unroll
  for (int m = 0; m < 3; m++) {
    float* Om = (m==0) ? g_v : (m==1) ? g_bsrc : g_bdst;
    const float* ad = sAdd[m];
    float D[8][4];
    wgemmr_tf(Ah, g_fW[m+1], lane, D);
#pragma unroll
    for (int n8 = 0; n8 < 8; n8++) {
      int c0 = n8*8 + 2*q, c1 = c0 + 1;
      if (ok0) *(float2*)(Om + (nb+r)*64 + c0) =
          make_float2(D[n8][0] + ad[c0], D[n8][1] + ad[c1]);
      if (ok1) *(float2*)(Om + (nb+r+8)*64 + c0) =
          make_float2(D[n8][2] + ad[c0], D[n8][3] + ad[c1]);
    }
  }
}

// ---------------- K2: fused edge kernel (bf16 m16n8k16, M=16 per warp) ------
// smem words:
//  [0,4096)        Wp2|Wfuse interleaved bf16 frag pairs (uint4/lane)
//  [4096,6144)     Wa2 bf16 frag-linear (uint2/lane)
//  [6144,18432)    8 per-warp scratch (1536 each): g[16x76] / epi2 2x[16x40]
//  [18432,18688)   Wp1 packed float4 per col {w0,w1,w2,bp1}
//  [18688,18752)   ba2
//  [18752,19136)   8 per-warp rel (48 each)
//  [19136,19392)   8 per-warp src/dst (32 each)
#define SM_WORDS 19392
__global__ void __launch_bounds__(256, 2) k_edge(
    const float* __restrict__ pos, const int* __restrict__ eidx,
    const float* __restrict__ Wp1, const float* __restrict__ bp1,
    const float* __restrict__ Wp2, const float* __restrict__ Wa2,
    const float* __restrict__ ba2) {
  extern __shared__ uint32_t smu[];
  uint32_t* sW12  = smu;                    // 4096
  uint32_t* sW3   = smu + 4096;             // 2048
  float*    sScr  = (float*)(smu + 6144);   // 12288
  float4*   sWp1p = (float4*)(smu + 18432); // 64 float4
  float* sba2 = (float*)(smu + 18688);
  float* sRelAll = (float*)(smu + 18752);
  int*   sIdxAll = (int*)(smu + 19136);

  int tid = threadIdx.x;
  int wid = tid >> 5, lane = tid & 31;

  for (int idx = tid; idx < 2048; idx += 256) {
    int t  = idx & 1;
    int ln = (idx >> 1) & 31;
    int fr = idx >> 6;
    int ks = fr >> 3, n8 = fr & 7;
    int rr = ln >> 2, qq = ln & 3;
    int klo = 16*ks + 2*qq + t*8;
    int col = 8*n8 + rr;
    uint32_t w1 = packbf(Wp2[klo*64 + col],     Wp2[(klo+1)*64 + col]);
    uint32_t w2 = packbf(g_Wfuse[klo*64 + col], g_Wfuse[(klo+1)*64 + col]);
    uint32_t w3 = packbf(Wa2[klo*64 + col],     Wa2[(klo+1)*64 + col]);
    int base12 = (fr << 7) + (ln << 2);
    sW12[base12 + t]     = w1;
    sW12[base12 + 2 + t] = w2;
    sW3[(fr << 6) + (ln << 1) + t] = w3;
  }
  if (tid < 64) {
    sWp1p[tid] = make_float4(Wp1[tid], Wp1[64+tid], Wp1[128+tid], bp1[tid]);
    sba2[tid] = ba2[tid];
  }
  __syncthreads();

  float* scr = sScr + wid*1536;
  float* sRel = sRelAll + wid*48;
  int* sS = sIdxAll + wid*32;
  int* sD = sS + 16;

  int r = lane >> 2, q = lane & 3;
  int eg = lane >> 3, c8 = lane & 7;

  int gw = blockIdx.x * 8 + wid;
  int nwarp = gridDim.x * 8;
  for (int t = gw; t < NT16; t += nwarp) {
    int eb = t * 16;
    if (lane < 16) sS[lane] = eidx[eb + lane];
    else           sD[lane - 16] = eidx[EE + eb + (lane - 16)];
    __syncwarp();
    if (lane < 16) {
      int s = sS[lane], d = sD[lane];
      sRel[lane]      = pos[d*3+0] - pos[s*3+0];
      sRel[16 + lane] = pos[d*3+1] - pos[s*3+1];
      sRel[32 + lane] = pos[d*3+2] - pos[s*3+2];
    }
    __syncwarp();

    float rx0 = sRel[r],     ry0 = sRel[16+r],   rz0 = sRel[32+r];
    float rx1 = sRel[r+8],   ry1 = sRel[16+r+8], rz1 = sRel[32+r+8];
    uint32_t At[4][4];
#pragma unroll
    for (int ks = 0; ks < 4; ks++) {
      float4 wA = sWp1p[16*ks + 2*q];
      float4 wB = sWp1p[16*ks + 2*q + 1];
      float4 wC = sWp1p[16*ks + 2*q + 8];
      float4 wD = sWp1p[16*ks + 2*q + 9];
      float tA0 = fmaxf(fmaf(rx0,wA.x,fmaf(ry0,wA.y,fmaf(rz0,wA.z,wA.w))),0.f);
      float tB0 = fmaxf(fmaf(rx0,wB.x,fmaf(ry0,wB.y,fmaf(rz0,wB.z,wB.w))),0.f);
      float tA1 = fmaxf(fmaf(rx1,wA.x,fmaf(ry1,wA.y,fmaf(rz1,wA.z,wA.w))),0.f);
      float tB1 = fmaxf(fmaf(rx1,wB.x,fmaf(ry1,wB.y,fmaf(rz1,wB.z,wB.w))),0.f);
      float tC0 = fmaxf(fmaf(rx0,wC.x,fmaf(ry0,wC.y,fmaf(rz0,wC.z,wC.w))),0.f);
      float tD0 = fmaxf(fmaf(rx0,wD.x,fmaf(ry0,wD.y,fmaf(rz0,wD.z,wD.w))),0.f);
      float tC1 = fmaxf(fmaf(rx1,wC.x,fmaf(ry1,wC.y,fmaf(rz1,wC.z,wC.w))),0.f);
      float tD1 = fmaxf(fmaf(rx1,wD.x,fmaf(ry1,wD.y,fmaf(rz1,wD.z,wD.w))),0.f);
      At[ks][0] = packbf(tA0, tB0);
      At[ks][1] = packbf(tA1, tB1);
      At[ks][2] = packbf(tC0, tD0);
      At[ks][3] = packbf(tC1, tD1);
    }

    float D1[8][4], D2[8][4];
    wgemm2rb(At, sW12, lane, D1, D2);

    // ---- epi1a: gather g = bdst - bsrc (cfuse folded into g_bdst) ----
#pragma unroll
    for (int h = 0; h < 2; h++) {
#pragma unroll
      for (int s4 = 0; s4 < 4; s4++) {
        int e = s4*4 + eg;
        int dn = sD[e], sn = sS[e];
        int cg = h*32 + c8*4;
        float4 bd = *(const float4*)(g_bdst + dn*64 + cg);
        float4 bs = *(const float4*)(g_bsrc + sn*64 + cg);
        *(float4*)(scr + e*76 + cg) = make_float4(
            bd.x - bs.x, bd.y - bs.y, bd.z - bs.z, bd.w - bs.w);
      }
    }
    __syncwarp();

    // ---- epi1b: u = relu(D2 + g); D-layout packs straight into A-frags ----
    uint32_t Au[4][4];
#pragma unroll
    for (int ks = 0; ks < 4; ks++) {
      int na = 2*ks, nb = 2*ks + 1;
      float2 g0a = *(const float2*)(scr + r*76 + na*8 + 2*q);
      float2 g1a = *(const float2*)(scr + (r+8)*76 + na*8 + 2*q);
      float2 g0b = *(const float2*)(scr + r*76 + nb*8 + 2*q);
      float2 g1b = *(const float2*)(scr + (r+8)*76 + nb*8 + 2*q);
      Au[ks][0] = packbf(fmaxf(D2[na][0] + g0a.x, 0.f),
                         fmaxf(D2[na][1] + g0a.y, 0.f));
      Au[ks][1] = packbf(fmaxf(D2[na][2] + g1a.x, 0.f),
                         fmaxf(D2[na][3] + g1a.y, 0.f));
      Au[ks][2] = packbf(fmaxf(D2[nb][0] + g0b.x, 0.f),
                         fmaxf(D2[nb][1] + g0b.y, 0.f));
      Au[ks][3] = packbf(fmaxf(D2[nb][2] + g1b.x, 0.f),
                         fmaxf(D2[nb][3] + g1b.y, 0.f));
    }
    __syncwarp();

    float D3[8][4];
    wgemmrb(Au, sW3, lane, D3);

    // ---- epi2: e = exp(D3+ba2); red g_sum += e; g_num += e*(v+D1) ----
    float* sH1 = scr;
    float* sH3 = scr + 640;
#pragma unroll
    for (int h = 0; h < 2; h++) {
#pragma unroll
      for (int n8l = 0; n8l < 4; n8l++) {
        int n8 = h*4 + n8l;
        *(float2*)(sH1 + r*40 + n8l*8 + 2*q)     = make_float2(D1[n8][0], D1[n8][1]);
        *(float2*)(sH1 + (r+8)*40 + n8l*8 + 2*q) = make_float2(D1[n8][2], D1[n8][3]);
        *(float2*)(sH3 + r*40 + n8l*8 + 2*q)     = make_float2(D3[n8][0], D3[n8][1]);
        *(float2*)(sH3 + (r+8)*40 + n8l*8 + 2*q) = make_float2(D3[n8][2], D3[n8][3]);
      }
      __syncwarp();
#pragma unroll
      for (int s4 = 0; s4 < 4; s4++) {
        int e = s4*4 + eg;
        int dn = sD[e], sn = sS[e];
        int cg = h*32 + c8*4;
        float4 lg = *(const float4*)(sH3 + e*40 + c8*4);
        float4 d1 = *(const float4*)(sH1 + e*40 + c8*4);
        float4 vv = *(const float4*)(g_v + sn*64 + cg);   // bp2 folded in
        float4 ba = *(const float4*)(sba2 + cg);
        float e0 = __expf(lg.x + ba.x);
        float e1 = __expf(lg.y + ba.y);
        float e2 = __expf(lg.z + ba.z);
        float e3 = __expf(lg.w + ba.w);
        redv4(g_sum + dn*64 + cg, e0, e1, e2, e3);
        redv4(g_num + dn*64 + cg,
              e0 * (vv.x + d1.x), e1 * (vv.y + d1.y),
              e2 * (vv.z + d1.z), e3 * (vv.w + d1.w));
      }
      __syncwarp();
    }
  }
}

// ---------------- K3: out = relu((num/(sum+eps))@W_out + b_out), tf32 -------
__global__ __launch_bounds__(256, 3) void k_final(const float* __restrict__ bout,
                                                  float* __restrict__ out) {
  __shared__ float sXall[8*1088];
  __shared__ float sbout[64];

  int tid = threadIdx.x;
  int wid = tid >> 5, lane = tid & 31;
  int nb = blockIdx.x * 128 + wid*16;

  if (tid < 64) sbout[tid] = bout[tid];
  __syncthreads();

  if (nb >= NN) return;
  float* sX = sXall + wid*1088;

  for (int idx = lane; idx < 256; idx += 32) {
    int row = idx >> 4;
    int c4  = (idx & 15) << 2;
    int n = nb + row;
    float4 v = make_float4(0.f,0.f,0.f,0.f);
    if (n < NN) {
      float4 num = *(const float4*)(g_num + n*64 + c4);
      float4 s   = *(const float4*)(g_sum + n*64 + c4);
      v.x = num.x / (s.x + 1e-16f);
      v.y = num.y / (s.y + 1e-16f);
      v.z = num.z / (s.z + 1e-16f);
      v.w = num.w / (s.w + 1e-16f);
    }
    *(float4*)(sX + row*68 + c4) = v;
  }
  __syncwarp();

  int r = lane >> 2, q = lane & 3;
  uint32_t Ax[8][4];
#pragma unroll
  for (int k8 = 0; k8 < 8; k8++) {
    Ax[k8][0] = f2tf(sX[r*68     + k8*8 + q]);
    Ax[k8][1] = f2tf(sX[(r+8)*68 + k8*8 + q]);
    Ax[k8][2] = f2tf(sX[r*68     + k8*8 + q + 4]);
    Ax[k8][3] = f2tf(sX[(r+8)*68 + k8*8 + q + 4]);
  }

  float D[8][4];
  wgemmr_tf(Ax, g_fW[4], lane, D);

  int ok0 = (nb + r < NN), ok1 = (nb + r + 8 < NN);
#pragma unroll
  for (int n8 = 0; n8 < 8; n8++) {
    int c0 = n8*8 + 2*q, c1 = c0 + 1;
    if (ok0)
      *(float2*)(out + (nb+r)*64 + c0) = make_float2(
          fmaxf(D[n8][0] + sbout[c0], 0.f), fmaxf(D[n8][1] + sbout[c1], 0.f));
    if (ok1)
      *(float2*)(out + (nb+r+8)*64 + c0) = make_float2(
          fmaxf(D[n8][2] + sbout[c0], 0.f), fmaxf(D[n8][3] + sbout[c1], 0.f));
  }
}

// ---------------- launch ----------------
extern "C" void kernel_launch(void* const* d_in, const int* in_sizes, int n_in,
                              void* d_out, int out_size) {
  const float* x    = (const float*)d_in[0];
  const float* pos  = (const float*)d_in[1];
  const int*   eidx = (const int*)  d_in[2];
  const float* W_in = (const float*)d_in[3];
  const float* b_in = (const float*)d_in[4];
  const float* W_lin= (const float*)d_in[5];
  const float* W_src= (const float*)d_in[6];
  const float* W_dst= (const float*)d_in[7];
  const float* Wp1  = (const float*)d_in[8];
  const float* bp1  = (const float*)d_in[9];
  const float* Wp2  = (const float*)d_in[10];
  const float* bp2  = (const float*)d_in[11];
  const float* Wa1  = (const float*)d_in[12];
  const float* ba1  = (const float*)d_in[13];
  const float* Wa2  = (const float*)d_in[14];
  const float* ba2  = (const float*)d_in[15];
  const float* W_out= (const float*)d_in[16];
  const float* b_out= (const float*)d_in[17];
  float* out = (float*)d_out;

  cudaFuncSetAttribute(k_edge, cudaFuncAttributeMaxDynamicSharedMemorySize,
                       SM_WORDS * 4);

  kw<<<3, 256>>>(W_src, W_dst, Wp2, Wa1, bp2, ba1);
  kw2<<<5, 256>>>(W_in, W_lin, W_out);
  k_node<<<(NN + 127) / 128, 256>>>(x, b_in, bp2);
  k_edge<<<296, 256, SM_WORDS * 4>>>(pos, eidx, Wp1, bp1, Wp2, Wa2, ba2);
  k_final<<<(NN + 127) / 128, 256>>>(b_out, out);
}